// round 4
// baseline (speedup 1.0000x reference)
#include <cuda_runtime.h>
#include <cuda_bf16.h>

// SignAdaptor: fused repeat/gather/concat/pad — single kernel, 4 rows/CTA.
//   out[b, j, 0:1024]    = image_batch[foff[b] + j]                (j < nf[b])
//   out[b, j, 1024:2048] = clip_batch [coff[b] + min(j/rf, nc-1)]  (j < nf[b])
//   out[b, j, :]         = pad_idx                                 (j >= nf[b])
//   src_length[b]        = nf[b]   (appended after x when present)
//
// HBM-bound. Each CTA (256 thr) handles 4 consecutive rows of one batch:
// every thread front-batches 8 independent 16B loads (MLP=8), then 8 stores.
// Prefix offsets recomputed per-warp via register scan (no smem, no barrier).

#define B_CONST 32
#define RPC 4                 // rows per CTA

__global__ __launch_bounds__(256)
void gather4_kernel(const float* __restrict__ img,
                    const float* __restrict__ clip,
                    const int* __restrict__ nf,
                    const int* __restrict__ nc,
                    const int* __restrict__ pad,   // may be null -> 0
                    float* __restrict__ out,
                    int L, long long src_off, int has_src) {
    const int b  = blockIdx.y;
    const int j0 = blockIdx.x * RPC;
    const int t  = threadIdx.x;           // 0..255
    const int lane = t & 31;

    // ---- per-warp redundant exclusive scan of nf/nc over B=32 ----
    int f = nf[lane];
    int c = nc[lane];
    int fs = f, cs = c;
    #pragma unroll
    for (int o = 1; o < 32; o <<= 1) {
        int vf = __shfl_up_sync(0xffffffffu, fs, o);
        int vc = __shfl_up_sync(0xffffffffu, cs, o);
        if (lane >= o) { fs += vf; cs += vc; }
    }
    const int foff_b = __shfl_sync(0xffffffffu, fs - f, b);
    const int coff_b = __shfl_sync(0xffffffffu, cs - c, b);
    const int n      = __shfl_sync(0xffffffffu, f, b);
    const int cnum   = __shfl_sync(0xffffffffu, c, b);

    const int rf   = n / cnum;
    const int cmax = cnum - 1;

    const float  pv = pad ? (float)pad[0] : 0.0f;
    const float4 p4 = make_float4(pv, pv, pv, pv);

    // ---- phase 1: batch all loads (up to 8 independent LDG.128) ----
    float4 iv[RPC], cv[RPC];
    #pragma unroll
    for (int r = 0; r < RPC; r++) {
        const int j = j0 + r;
        if (j < n) {
            const float4* isrc =
                (const float4*)(img + ((long long)(foff_b + j)) * 1024);
            int cidx = j / rf;
            if (cidx > cmax) cidx = cmax;
            const float4* csrc =
                (const float4*)(clip + ((long long)(coff_b + cidx)) * 1024);
            iv[r] = __ldcs(isrc + t);   // read-once: don't pollute L2
            cv[r] = __ldg(csrc + t);    // 4x reuse: keep in L2
        } else {
            iv[r] = p4;
            cv[r] = p4;
        }
    }

    // ---- phase 2: stores ----
    float4* __restrict__ obase =
        (float4*)(out + ((long long)b * L + j0) * 2048);
    #pragma unroll
    for (int r = 0; r < RPC; r++) {
        const int j = j0 + r;
        if (j < L) {
            obase[r * 512 + t]       = iv[r];
            obase[r * 512 + 256 + t] = cv[r];
        }
    }

    if (has_src && j0 == 0 && t == 0) {
        out[src_off + b] = (float)n;
    }
}

extern "C" void kernel_launch(void* const* d_in, const int* in_sizes, int n_in,
                              void* d_out, int out_size) {
    const float* img  = (const float*)d_in[0];   // image_batch [tf, 1024]
    // d_in[1] = emo_batch (unused by reference)
    const float* clip = (const float*)d_in[2];   // clip_batch  [tc, 1024]
    const int*   nf   = (const int*)d_in[3];     // [32]
    const int*   nc   = (const int*)d_in[4];     // [32]
    const int*   pad  = (n_in >= 6) ? (const int*)d_in[5] : nullptr;

    float* out = (float*)d_out;

    // out_size = B*L*2048 (+ B if src_length is part of the flattened output)
    const long long per = (long long)B_CONST * 2048;
    long long L;
    int has_src;
    if ((long long)out_size % per == 0) {
        L = (long long)out_size / per;
        has_src = 0;
    } else {
        L = ((long long)out_size - B_CONST) / per;
        has_src = 1;
    }

    dim3 grid((unsigned)((L + RPC - 1) / RPC), B_CONST);
    gather4_kernel<<<grid, 256>>>(img, clip, nf, nc, pad, out,
                                  (int)L, (long long)B_CONST * L * 2048,
                                  has_src);
}